// round 5
// baseline (speedup 1.0000x reference)
#include <cuda_runtime.h>
#include <math.h>

// Problem constants
#define B_    32
#define S_    512
#define DIN_  512
#define DH_   1024
#define DOUT_ 512
#define NG_   4096   // 4 * DH_

// Persistent-kernel geometry
#define NCTA_     128
#define SLABK     128                 // k per slab
#define NSLAB     8
#define HD_STRIDE 258                 // floats per batch row in duplicated h buffer (2*128+2)
#define HBUF_F    (32 * HD_STRIDE)    // 8256 floats per h buffer
#define WS_F      (DH_ * 32)          // 32768 floats of W slice [k][col]
#define REDW      1056                // floats per warp in reduction region (16 slots * 66)
#define SMEM_F    (WS_F + 2 * HBUF_F + 256)
#define SMEM_BYTES (SMEM_F * 4)       // 198,144 B

// -------- scratch (device globals; no allocation allowed) --------
__device__ float g_gatesx[S_ * B_ * NG_];   // [t][b][4096]
__device__ float g_hs[S_ * B_ * DH_];       // [t][b][1024]
__device__ float g_hb0[B_ * DH_];
__device__ float g_hb1[B_ * DH_];
__device__ unsigned g_bar;

// ---------------- f32x2 helpers ----------------
__device__ __forceinline__ void ffma2(unsigned long long& d,
                                      const unsigned long long a,
                                      const unsigned long long b) {
    asm("fma.rn.f32x2 %0, %1, %2, %3;" : "=l"(d) : "l"(a), "l"(b), "l"(d));
}
__device__ __forceinline__ unsigned long long pack2(float lo, float hi) {
    unsigned long long r;
    asm("mov.b64 %0, {%1, %2};" : "=l"(r) : "f"(lo), "f"(hi));
    return r;
}
__device__ __forceinline__ float2 unpack2(unsigned long long v) {
    float2 r;
    asm("mov.b64 {%0, %1}, %2;" : "=f"(r.x), "=f"(r.y) : "l"(v));
    return r;
}

__device__ __forceinline__ float sigf(float x) {
    return __fdividef(1.0f, 1.0f + __expf(-x));
}
__device__ __forceinline__ float tanhfast(float x) {
    return __fdividef(2.0f, 1.0f + __expf(-2.0f * x)) - 1.0f;
}

// ----------------------------------------------------------------
__global__ void init_state_kernel() {
    int i = blockIdx.x * blockDim.x + threadIdx.x;
    if (i < B_ * DH_) g_hb0[i] = 0.0f;
    if (i == 0) g_bar = 0u;
}

// ----------------------------------------------------------------
// Phase 1: gates_x = x @ Wx(4 gates) + bias
// Tile 64m x 128n x 16k, 256 threads, microtile 4m x 8n, FFMA2.
// As duplicated: [k][2m] stride 130; Bs: [k][n] stride 132.
// ----------------------------------------------------------------
__global__ __launch_bounds__(256)
void gemm_gatesx_kernel(const float* __restrict__ x,
                        const float* __restrict__ Wf, const float* __restrict__ bf,
                        const float* __restrict__ Wi, const float* __restrict__ bi,
                        const float* __restrict__ Wg, const float* __restrict__ bg,
                        const float* __restrict__ Wo, const float* __restrict__ bo)
{
    const int n0 = blockIdx.x * 128;         // 0..3968 (within one gate: 128 | 1024)
    const int m0 = blockIdx.y * 64;

    const int gate  = n0 >> 10;
    const int jbase = n0 & 1023;
    const float* W    = (gate == 0) ? Wf : (gate == 1) ? Wi : (gate == 2) ? Wg : Wo;
    const float* bias = (gate == 0) ? bf : (gate == 1) ? bi : (gate == 2) ? bg : bo;

    __shared__ float As[16 * 130];   // duplicated A: [k][2m]
    __shared__ float Bs[16 * 132];   // [k][n]

    const int tid = threadIdx.x;
    const int tx  = tid & 15;
    const int ty  = tid >> 4;

    // A loader: one float4 per thread
    const int lm  = tid >> 2;           // 0..63
    const int lk4 = (tid & 3) * 4;      // 0,4,8,12
    const int m_a = m0 + lm;
    const int b_a = m_a & 31;
    const int t_a = m_a >> 5;
    const float* xrow = x + ((size_t)b_a * S_ + t_a) * DIN_;

    unsigned long long acc2[4][4];
#pragma unroll
    for (int i = 0; i < 4; i++)
#pragma unroll
        for (int j = 0; j < 4; j++) acc2[i][j] = 0ull;

    for (int k0 = 0; k0 < DIN_; k0 += 16) {
        __syncthreads();
        // A tile -> duplicated smem
        float4 av = *reinterpret_cast<const float4*>(xrow + k0 + lk4);
        *reinterpret_cast<unsigned long long*>(&As[(lk4 + 0) * 130 + 2 * lm]) = pack2(av.x, av.x);
        *reinterpret_cast<unsigned long long*>(&As[(lk4 + 1) * 130 + 2 * lm]) = pack2(av.y, av.y);
        *reinterpret_cast<unsigned long long*>(&As[(lk4 + 2) * 130 + 2 * lm]) = pack2(av.z, av.z);
        *reinterpret_cast<unsigned long long*>(&As[(lk4 + 3) * 130 + 2 * lm]) = pack2(av.w, av.w);
        // B tile: 16 rows x 128 cols
#pragma unroll
        for (int p = 0; p < 2; p++) {
            const int f  = tid + p * 256;
            const int r  = f >> 5;
            const int c4 = (f & 31) * 4;
            *reinterpret_cast<float4*>(&Bs[r * 132 + c4]) =
                *reinterpret_cast<const float4*>(W + (size_t)(k0 + r) * DH_ + jbase + c4);
        }
        __syncthreads();

#pragma unroll
        for (int kk = 0; kk < 16; kk++) {
            unsigned long long a2[4], b2[4];
#pragma unroll
            for (int i = 0; i < 4; i++)
                a2[i] = *reinterpret_cast<const unsigned long long*>(
                    &As[kk * 130 + 2 * (ty * 4 + i)]);
#pragma unroll
            for (int jp = 0; jp < 4; jp++)
                b2[jp] = *reinterpret_cast<const unsigned long long*>(
                    &Bs[kk * 132 + 2 * tx + 32 * jp]);
#pragma unroll
            for (int i = 0; i < 4; i++)
#pragma unroll
                for (int jp = 0; jp < 4; jp++)
                    ffma2(acc2[i][jp], a2[i], b2[jp]);
        }
    }

#pragma unroll
    for (int i = 0; i < 4; i++) {
        const int row = m0 + ty * 4 + i;
#pragma unroll
        for (int jp = 0; jp < 4; jp++) {
            const int c0 = 2 * tx + 32 * jp;
            float2 v = unpack2(acc2[i][jp]);
            const float2 bv = *reinterpret_cast<const float2*>(&bias[jbase + c0]);
            float2 o;
            o.x = v.x + bv.x;
            o.y = v.y + bv.y;
            *reinterpret_cast<float2*>(&g_gatesx[(size_t)row * NG_ + n0 + c0]) = o;
        }
    }
}

// ----------------------------------------------------------------
// Phase 2: PERSISTENT recurrence kernel (FFMA2 version).
// 128 CTAs x 256 thr. CTA owns 32 cols (8 j x 4 gates); W slice [k][col]
// resident in SMEM. Per step: h loaded from L2 into DUPLICATED smem slabs
// of 128 k, double-buffered. Thread tile: 4 batches (bg=lane&7) x
// 8 cols (cg=lane>>3), accumulated as 4x4 f32x2 pairs.
// Cross-warp k-reduction in smem (aliased over h buffers), elementwise
// update, software grid barrier.
// ----------------------------------------------------------------
__global__ __launch_bounds__(256, 1)
void lstm_persist_kernel(const float* __restrict__ Wf, const float* __restrict__ Wi,
                         const float* __restrict__ Wg, const float* __restrict__ Wo)
{
    extern __shared__ float smem[];
    float* w_s   = smem;                      // [k*32 + col]
    float* h_buf = smem + WS_F;               // 2 x HBUF_F, dup layout [b*258 + 2k(+1)]
    float* red_s = h_buf;                     // alias after slabs done (needs 8448 <= 16512)
    float* c_s   = smem + WS_F + 2 * HBUF_F;  // 256 floats

    const int tid  = threadIdx.x;
    const int lane = tid & 31;
    const int warp = tid >> 5;
    const int j0   = blockIdx.x * 8;

    // worker tile: 8 batch-groups of 4 x 4 col-groups of 8
    const int bg = lane & 7;
    const int cg = lane >> 3;

    // ---- one-time: load W slice into SMEM [k][col], col = jj*4+gate ----
    for (int idx = tid; idx < WS_F; idx += 256) {
        const int k    = idx >> 5;
        const int c    = idx & 31;
        const int jj   = c >> 2;
        const int gate = c & 3;
        const float* Wsel = (gate == 0) ? Wf : (gate == 1) ? Wi : (gate == 2) ? Wg : Wo;
        w_s[idx] = Wsel[(size_t)(512 + k) * DH_ + j0 + jj];
    }
    c_s[tid] = 0.0f;
    __syncthreads();

    // elementwise mapping
    const int b_e  = tid >> 3;
    const int jj_e = tid & 7;

    volatile unsigned* barp = &g_bar;

    for (int t = 0; t < S_; ++t) {
        const float* __restrict__ h_in  = (t & 1) ? g_hb1 : g_hb0;
        float*       __restrict__ h_out = (t & 1) ? g_hb0 : g_hb1;
        const float* __restrict__ gx_t  = g_gatesx + (size_t)t * B_ * NG_;

        // prefetch gates_x epilogue values early
        float gxv[4];
#pragma unroll
        for (int g = 0; g < 4; g++)
            gxv[g] = __ldg(&gx_t[(size_t)b_e * NG_ + g * DH_ + j0 + jj_e]);

        unsigned long long acc2[4][4];
#pragma unroll
        for (int i = 0; i < 4; i++)
#pragma unroll
            for (int j = 0; j < 4; j++) acc2[i][j] = 0ull;

        // ---- load slab 0 (duplicated) ----
        {
            float* db = h_buf;
#pragma unroll
            for (int p = 0; p < 4; p++) {
                const int idx = tid + p * 256;     // 0..1023
                const int b   = idx >> 5;          // 0..31
                const int k4  = (idx & 31) * 4;    // 0..124
                const float4 v = __ldcg(reinterpret_cast<const float4*>(
                    &h_in[(size_t)b * DH_ + k4]));
                unsigned long long* dst = reinterpret_cast<unsigned long long*>(
                    &db[b * HD_STRIDE + 2 * k4]);
                dst[0] = pack2(v.x, v.x);
                dst[1] = pack2(v.y, v.y);
                dst[2] = pack2(v.z, v.z);
                dst[3] = pack2(v.w, v.w);
            }
        }
        __syncthreads();

#pragma unroll
        for (int s = 0; s < NSLAB; ++s) {
            // prefetch next slab into registers
            float4 pf[4];
            if (s < NSLAB - 1) {
#pragma unroll
                for (int p = 0; p < 4; p++) {
                    const int idx = tid + p * 256;
                    const int b   = idx >> 5;
                    const int k4  = (idx & 31) * 4;
                    pf[p] = __ldcg(reinterpret_cast<const float4*>(
                        &h_in[(size_t)b * DH_ + (s + 1) * SLABK + k4]));
                }
            }

            // compute slab s: warp handles k_local in [warp*16, warp*16+16)
            {
                const float* hb = h_buf + (s & 1) * HBUF_F + (bg * 4) * HD_STRIDE
                                + 2 * (warp * 16);
                const float* wp = w_s + (size_t)(s * SLABK + warp * 16) * 32 + cg * 8;
#pragma unroll
                for (int kk = 0; kk < 16; ++kk) {
                    unsigned long long h2[4], w2[4];
#pragma unroll
                    for (int i = 0; i < 4; i++)
                        h2[i] = *reinterpret_cast<const unsigned long long*>(
                            hb + i * HD_STRIDE + 2 * kk);
#pragma unroll
                    for (int cp = 0; cp < 4; cp++)
                        w2[cp] = *reinterpret_cast<const unsigned long long*>(
                            wp + kk * 32 + 2 * cp);
#pragma unroll
                    for (int i = 0; i < 4; i++)
#pragma unroll
                        for (int cp = 0; cp < 4; cp++)
                            ffma2(acc2[i][cp], h2[i], w2[cp]);
                }
            }

            if (s < NSLAB - 1) {
                float* db = h_buf + ((s + 1) & 1) * HBUF_F;
#pragma unroll
                for (int p = 0; p < 4; p++) {
                    const int idx = tid + p * 256;
                    const int b   = idx >> 5;
                    const int k4  = (idx & 31) * 4;
                    unsigned long long* dst = reinterpret_cast<unsigned long long*>(
                        &db[b * HD_STRIDE + 2 * k4]);
                    dst[0] = pack2(pf[p].x, pf[p].x);
                    dst[1] = pack2(pf[p].y, pf[p].y);
                    dst[2] = pack2(pf[p].z, pf[p].z);
                    dst[3] = pack2(pf[p].w, pf[p].w);
                }
                __syncthreads();
            }
        }
        __syncthreads();   // h buffers now free -> reuse as reduction space

        // ---- cross-warp reduction: packed stores ----
        // slot2 = i*4 + cp, float2 addr = warp*REDW + slot2*66 + lane*2
#pragma unroll
        for (int i = 0; i < 4; i++)
#pragma unroll
            for (int cp = 0; cp < 4; cp++)
                *reinterpret_cast<unsigned long long*>(
                    &red_s[warp * REDW + (i * 4 + cp) * 66 + lane * 2]) = acc2[i][cp];
        __syncthreads();

        // ---- final sum + LSTM elementwise (thread owns (b_e, jj_e)) ----
        float z[4];
#pragma unroll
        for (int g = 0; g < 4; g++) {
            const int c    = jj_e * 4 + g;      // col index 0..31
            const int cgc  = c >> 3;
            const int rem  = c & 7;
            const int cp   = rem >> 1;
            const int half = rem & 1;
            const int i    = b_e & 3;
            const int lanec = cgc * 8 + (b_e >> 2);
            const int base = (i * 4 + cp) * 66 + lanec * 2 + half;
            float ssum = 0.0f;
#pragma unroll
            for (int w = 0; w < 8; w++)
                ssum += red_s[w * REDW + base];
            z[g] = ssum + gxv[g];
        }

        const float fg = sigf(z[0]);
        const float ig = sigf(z[1]);
        const float gg = tanhfast(z[2]);
        const float og = sigf(z[3]);

        const float cn = fg * c_s[tid] + ig * gg;
        c_s[tid] = cn;
        const float hn = og * tanhfast(cn);

        const int gj = j0 + jj_e;
        h_out[(size_t)b_e * DH_ + gj] = hn;
        g_hs[(size_t)t * B_ * DH_ + (size_t)b_e * DH_ + gj] = hn;

        // ---- grid barrier ----
        __syncthreads();
        if (t < S_ - 1) {
            if (tid == 0) {
                __threadfence();
                atomicAdd((unsigned*)&g_bar, 1u);
                const unsigned target = (unsigned)(NCTA_ * (t + 1));
                while (*barp < target) { }
                __threadfence();
            }
            __syncthreads();
        }
    }
}

// ----------------------------------------------------------------
// Phase 3: out = hs @ W_fc + b_fc  (64m x 128n x 16k FFMA2, K=1024)
// ----------------------------------------------------------------
__global__ __launch_bounds__(256)
void gemm_fc_kernel(const float* __restrict__ Wfc, const float* __restrict__ bfc,
                    float* __restrict__ out)
{
    const int n0 = blockIdx.x * 128;   // 0..384
    const int m0 = blockIdx.y * 64;

    __shared__ float As[16 * 130];
    __shared__ float Bs[16 * 132];

    const int tid = threadIdx.x;
    const int tx  = tid & 15;
    const int ty  = tid >> 4;

    const int lm  = tid >> 2;
    const int lk4 = (tid & 3) * 4;
    const float* arow = g_hs + (size_t)(m0 + lm) * DH_;

    unsigned long long acc2[4][4];
#pragma unroll
    for (int i = 0; i < 4; i++)
#pragma unroll
        for (int j = 0; j < 4; j++) acc2[i][j] = 0ull;

    for (int k0 = 0; k0 < DH_; k0 += 16) {
        __syncthreads();
        float4 av = *reinterpret_cast<const float4*>(arow + k0 + lk4);
        *reinterpret_cast<unsigned long long*>(&As[(lk4 + 0) * 130 + 2 * lm]) = pack2(av.x, av.x);
        *reinterpret_cast<unsigned long long*>(&As[(lk4 + 1) * 130 + 2 * lm]) = pack2(av.y, av.y);
        *reinterpret_cast<unsigned long long*>(&As[(lk4 + 2) * 130 + 2 * lm]) = pack2(av.z, av.z);
        *reinterpret_cast<unsigned long long*>(&As[(lk4 + 3) * 130 + 2 * lm]) = pack2(av.w, av.w);
#pragma unroll
        for (int p = 0; p < 2; p++) {
            const int f  = tid + p * 256;
            const int r  = f >> 5;
            const int c4 = (f & 31) * 4;
            *reinterpret_cast<float4*>(&Bs[r * 132 + c4]) =
                *reinterpret_cast<const float4*>(Wfc + (size_t)(k0 + r) * DOUT_ + n0 + c4);
        }
        __syncthreads();

#pragma unroll
        for (int kk = 0; kk < 16; kk++) {
            unsigned long long a2[4], b2[4];
#pragma unroll
            for (int i = 0; i < 4; i++)
                a2[i] = *reinterpret_cast<const unsigned long long*>(
                    &As[kk * 130 + 2 * (ty * 4 + i)]);
#pragma unroll
            for (int jp = 0; jp < 4; jp++)
                b2[jp] = *reinterpret_cast<const unsigned long long*>(
                    &Bs[kk * 132 + 2 * tx + 32 * jp]);
#pragma unroll
            for (int i = 0; i < 4; i++)
#pragma unroll
                for (int jp = 0; jp < 4; jp++)
                    ffma2(acc2[i][jp], a2[i], b2[jp]);
        }
    }

#pragma unroll
    for (int i = 0; i < 4; i++) {
        const int m  = m0 + ty * 4 + i;
        const int bb = m & 31;
        const int tt = m >> 5;
        float* orow = out + ((size_t)bb * S_ + tt) * DOUT_;
#pragma unroll
        for (int jp = 0; jp < 4; jp++) {
            const int c0 = 2 * tx + 32 * jp;
            float2 v = unpack2(acc2[i][jp]);
            const float2 bv = *reinterpret_cast<const float2*>(&bfc[n0 + c0]);
            float2 o;
            o.x = v.x + bv.x;
            o.y = v.y + bv.y;
            *reinterpret_cast<float2*>(&orow[n0 + c0]) = o;
        }
    }
}

// ----------------------------------------------------------------
extern "C" void kernel_launch(void* const* d_in, const int* in_sizes, int n_in,
                              void* d_out, int out_size)
{
    const float* x   = (const float*)d_in[0];
    const float* Wf  = (const float*)d_in[1];
    const float* bf  = (const float*)d_in[2];
    const float* Wi  = (const float*)d_in[3];
    const float* bi  = (const float*)d_in[4];
    const float* Wg  = (const float*)d_in[5];
    const float* bg  = (const float*)d_in[6];
    const float* Wo  = (const float*)d_in[7];
    const float* bo  = (const float*)d_in[8];
    const float* Wfc = (const float*)d_in[9];
    const float* bfc = (const float*)d_in[10];
    float* out = (float*)d_out;

    static bool configured = false;
    if (!configured) {
        cudaFuncSetAttribute(lstm_persist_kernel,
                             cudaFuncAttributeMaxDynamicSharedMemorySize, SMEM_BYTES);
        configured = true;
    }

    init_state_kernel<<<(B_ * DH_ + 255) / 256, 256>>>();

    {
        dim3 grid(NG_ / 128, (B_ * S_) / 64);
        gemm_gatesx_kernel<<<grid, 256>>>(x, Wf, bf, Wi, bi, Wg, bg, Wo, bo);
    }

    lstm_persist_kernel<<<NCTA_, 256, SMEM_BYTES>>>(Wf, Wi, Wg, Wo);

    {
        dim3 grid(DOUT_ / 128, (B_ * S_) / 64);
        gemm_fc_kernel<<<grid, 256>>>(Wfc, bfc, out);
    }
}

// round 6
// speedup vs baseline: 2.0689x; 2.0689x over previous
#include <cuda_runtime.h>
#include <cuda_bf16.h>
#include <math.h>

// Problem constants
#define B_    32
#define S_    512
#define DIN_  512
#define DH_   1024
#define DOUT_ 512
#define NG_   4096   // 4 * DH_

#define NCTA_  128

// ---- persistent mma kernel smem layout (bytes) ----
#define ROWB      2064                  // h plane row stride: 1024*2 + 16 pad
#define HPLANE_B  (32 * ROWB)           // 66048
#define ZP_OFF    (2 * HPLANE_B)        // 132096
#define ZP_STRIDE 34                    // floats per zp row
#define ZP_B      (4 * 32 * ZP_STRIDE * 4)   // 17408
#define CS_OFF    (ZP_OFF + ZP_B)       // 149504
#define SMEM_P_BYTES (CS_OFF + 256 * 4) // 150528

// -------- scratch (device globals; no allocation allowed) --------
__device__ float g_gatesx[S_ * B_ * NG_];   // [t][b][4096] gates order g*1024+j
__device__ float g_hs[S_ * B_ * DH_];       // [t][b][1024]
__device__ __nv_bfloat16 g_hhi[2][B_ * DH_];
__device__ __nv_bfloat16 g_hlo[2][B_ * DH_];
__device__ unsigned g_bar;

// ---------------- helpers ----------------
__device__ __forceinline__ float sigf(float x) {
    return __fdividef(1.0f, 1.0f + __expf(-x));
}
__device__ __forceinline__ float tanhfast(float x) {
    return __fdividef(2.0f, 1.0f + __expf(-2.0f * x)) - 1.0f;
}
__device__ __forceinline__ unsigned s2u(const void* p) {
    return (unsigned)__cvta_generic_to_shared(p);
}
// pack (a,b) floats into bf16x2 hi-part and lo-part registers (a in low half)
__device__ __forceinline__ void split2(float a, float b, unsigned& hi, unsigned& lo) {
    __nv_bfloat16 ah = __float2bfloat16(a);
    __nv_bfloat16 bh = __float2bfloat16(b);
    float ar = a - __bfloat162float(ah);
    float br = b - __bfloat162float(bh);
    __nv_bfloat162 hv; hv.x = ah; hv.y = bh;
    __nv_bfloat162 lv; lv.x = __float2bfloat16(ar); lv.y = __float2bfloat16(br);
    hi = *reinterpret_cast<unsigned*>(&hv);
    lo = *reinterpret_cast<unsigned*>(&lv);
}
__device__ __forceinline__ void ldsm4(unsigned& r0, unsigned& r1, unsigned& r2,
                                      unsigned& r3, unsigned addr) {
    asm volatile("ldmatrix.sync.aligned.m8n8.x4.shared.b16 {%0,%1,%2,%3}, [%4];"
                 : "=r"(r0), "=r"(r1), "=r"(r2), "=r"(r3) : "r"(addr));
}
__device__ __forceinline__ void mma_bf16(float& c0, float& c1, float& c2, float& c3,
                                         unsigned a0, unsigned a1, unsigned a2, unsigned a3,
                                         unsigned b0, unsigned b1) {
    asm volatile("mma.sync.aligned.m16n8k16.row.col.f32.bf16.bf16.f32 "
                 "{%0,%1,%2,%3},{%4,%5,%6,%7},{%8,%9},{%0,%1,%2,%3};"
                 : "+f"(c0), "+f"(c1), "+f"(c2), "+f"(c3)
                 : "r"(a0), "r"(a1), "r"(a2), "r"(a3), "r"(b0), "r"(b1));
}
// FFMA2 helpers (kept for FC kernel only)
__device__ __forceinline__ void ffma2(unsigned long long& d,
                                      const unsigned long long a,
                                      const unsigned long long b) {
    asm("fma.rn.f32x2 %0, %1, %2, %3;" : "=l"(d) : "l"(a), "l"(b), "l"(d));
}
__device__ __forceinline__ unsigned long long pack2(float lo, float hi) {
    unsigned long long r;
    asm("mov.b64 %0, {%1, %2};" : "=l"(r) : "f"(lo), "f"(hi));
    return r;
}
__device__ __forceinline__ float2 unpack2(unsigned long long v) {
    float2 r;
    asm("mov.b64 {%0, %1}, %2;" : "=f"(r.x), "=f"(r.y) : "l"(v));
    return r;
}

// ----------------------------------------------------------------
__global__ void init_state_kernel() {
    int i = blockIdx.x * blockDim.x + threadIdx.x;
    if (i < B_ * DH_) {
        g_hhi[0][i] = __float2bfloat16(0.0f);
        g_hlo[0][i] = __float2bfloat16(0.0f);
    }
    if (i == 0) g_bar = 0u;
}

// ----------------------------------------------------------------
// Phase 1: gates_x = x @ Wx(4 gates) + bias  (R2 FFMA version — known good)
// ----------------------------------------------------------------
__global__ __launch_bounds__(256)
void gemm_gatesx_kernel(const float* __restrict__ x,
                        const float* __restrict__ Wf, const float* __restrict__ bf,
                        const float* __restrict__ Wi, const float* __restrict__ bi,
                        const float* __restrict__ Wg, const float* __restrict__ bg,
                        const float* __restrict__ Wo, const float* __restrict__ bo)
{
    const int n0 = blockIdx.x * 64;
    const int m0 = blockIdx.y * 64;

    const int gate  = n0 >> 10;
    const int jbase = n0 & 1023;
    const float* W    = (gate == 0) ? Wf : (gate == 1) ? Wi : (gate == 2) ? Wg : Wo;
    const float* bias = (gate == 0) ? bf : (gate == 1) ? bi : (gate == 2) ? bg : bo;

    __shared__ float As[16][65];
    __shared__ float Bs[16][64];

    const int tx = threadIdx.x;
    const int ty = threadIdx.y;
    const int tid = ty * 16 + tx;

    const int lm  = tid >> 2;
    const int lk4 = (tid & 3) * 4;
    const int m_a = m0 + lm;
    const int b_a = m_a & 31;
    const int t_a = m_a >> 5;
    const float* xrow = x + ((size_t)b_a * S_ + t_a) * DIN_;

    const int lkb = tid >> 4;
    const int ln4 = (tid & 15) * 4;

    float acc[4][4];
#pragma unroll
    for (int i = 0; i < 4; i++)
#pragma unroll
        for (int j = 0; j < 4; j++) acc[i][j] = 0.0f;

    for (int k0 = 0; k0 < DIN_; k0 += 16) {
        __syncthreads();
        float4 av = *reinterpret_cast<const float4*>(xrow + k0 + lk4);
        As[lk4 + 0][lm] = av.x;
        As[lk4 + 1][lm] = av.y;
        As[lk4 + 2][lm] = av.z;
        As[lk4 + 3][lm] = av.w;
        *reinterpret_cast<float4*>(&Bs[lkb][ln4]) =
            *reinterpret_cast<const float4*>(W + (size_t)(k0 + lkb) * DH_ + jbase + ln4);
        __syncthreads();

#pragma unroll
        for (int kk = 0; kk < 16; kk++) {
            float a[4], bvv[4];
#pragma unroll
            for (int i = 0; i < 4; i++) a[i]   = As[kk][ty * 4 + i];
#pragma unroll
            for (int j = 0; j < 4; j++) bvv[j] = Bs[kk][tx * 4 + j];
#pragma unroll
            for (int i = 0; i < 4; i++)
#pragma unroll
                for (int j = 0; j < 4; j++)
                    acc[i][j] = fmaf(a[i], bvv[j], acc[i][j]);
        }
    }

#pragma unroll
    for (int i = 0; i < 4; i++) {
        const int row = m0 + ty * 4 + i;
#pragma unroll
        for (int j = 0; j < 4; j++) {
            const int col = n0 + tx * 4 + j;
            g_gatesx[(size_t)row * NG_ + col] = acc[i][j] + bias[jbase + tx * 4 + j];
        }
    }
}

// ----------------------------------------------------------------
// Phase 2: PERSISTENT recurrence with bf16-split tensor-core MMA.
// 128 CTAs x 512 thr (16 warps). CTA owns 32 n-cols: c = gate*8 + jj,
// j = j0 + jj, j0 = blockIdx.x*8.
// Warp (kh = w>>2, gate = w&3): k range [kh*256, kh*256+256), one gate (8 n).
// W fragments (hi+lo bf16) preloaded into REGISTERS once: 64 regs/thread.
// Per step: stage h_hi/h_lo (bf16) into SMEM planes, ldmatrix A frags,
// 3-term mma into fp32 acc, 4-way k-reduction via SMEM, elementwise LSTM,
// software grid barrier.
// ----------------------------------------------------------------
__global__ __launch_bounds__(512, 1)
void lstm_persist_kernel(const float* __restrict__ Wf, const float* __restrict__ Wi,
                         const float* __restrict__ Wg, const float* __restrict__ Wo)
{
    extern __shared__ char smem[];
    char*  h_hi_s = smem;                         // 32 x ROWB bytes
    char*  h_lo_s = smem + HPLANE_B;
    float* zp     = reinterpret_cast<float*>(smem + ZP_OFF);   // [4][32][34]
    float* c_s    = reinterpret_cast<float*>(smem + CS_OFF);   // 256

    const int tid  = threadIdx.x;
    const int lane = tid & 31;
    const int warp = tid >> 5;
    const int j0   = blockIdx.x * 8;

    const int kh   = warp >> 2;       // 0..3  (k quarter: 256 k)
    const int gate = warp & 3;        // 0..3
    const float* Wsel = (gate == 0) ? Wf : (gate == 1) ? Wi : (gate == 2) ? Wg : Wo;

    // ---- one-time: W fragments into registers ----
    // B frag (m16n8k16 col-major): reg0 holds W[k0+kr, k0+kr+1][n], reg1 +8.
    // n = j0 + jj, jj = lane>>2 ; kr = (lane&3)*2
    const int jj = lane >> 2;
    const int kr = (lane & 3) * 2;
    unsigned wh[16][2], wl[16][2];
#pragma unroll
    for (int kt = 0; kt < 16; kt++) {
        const int kb = kh * 256 + kt * 16 + kr;
        const float w0a = Wsel[(size_t)(512 + kb + 0) * DH_ + j0 + jj];
        const float w0b = Wsel[(size_t)(512 + kb + 1) * DH_ + j0 + jj];
        const float w1a = Wsel[(size_t)(512 + kb + 8) * DH_ + j0 + jj];
        const float w1b = Wsel[(size_t)(512 + kb + 9) * DH_ + j0 + jj];
        split2(w0a, w0b, wh[kt][0], wl[kt][0]);
        split2(w1a, w1b, wh[kt][1], wl[kt][1]);
    }

    if (tid < 256) c_s[tid] = 0.0f;
    __syncthreads();

    // ldmatrix address components (per thread, constant across steps)
    // sel 0..3 -> (row+0,k+0),(row+8,k+0),(row+0,k+8),(row+8,k+8)
    const int sel    = lane >> 3;
    const int rowoff = ((sel & 1) * 8) + (lane & 7);
    const int koff   = (sel >> 1) * 8;

    const unsigned hs_hi_u = s2u(h_hi_s);
    const unsigned hs_lo_u = s2u(h_lo_s);

    // elementwise mapping (first 256 threads)
    const int b_e  = tid >> 3;
    const int jj_e = tid & 7;

    volatile unsigned* barp = &g_bar;

    for (int t = 0; t < S_; ++t) {
        const __nv_bfloat16* __restrict__ hhi_in = g_hhi[t & 1];
        const __nv_bfloat16* __restrict__ hlo_in = g_hlo[t & 1];
        __nv_bfloat16* __restrict__ hhi_out = g_hhi[(t + 1) & 1];
        __nv_bfloat16* __restrict__ hlo_out = g_hlo[(t + 1) & 1];
        const float* __restrict__ gx_t = g_gatesx + (size_t)t * B_ * NG_;

        // prefetch gates_x epilogue values (threads < 256)
        float gxv[4];
        if (tid < 256) {
#pragma unroll
            for (int g = 0; g < 4; g++)
                gxv[g] = __ldg(&gx_t[(size_t)b_e * NG_ + g * DH_ + j0 + jj_e]);
        }

        // ---- stage h planes into smem (bypass L1: other CTAs wrote them) ----
#pragma unroll
        for (int q = 0; q < 8; q++) {
            const int chunk = tid + q * 512;       // 0..4095, 16B chunks
            const int b = chunk >> 7;              // 0..31
            const int o = chunk & 127;             // 0..127 (x16B)
            const uint4 vh = __ldcg(reinterpret_cast<const uint4*>(
                hhi_in + (size_t)b * DH_) + o);
            const uint4 vl = __ldcg(reinterpret_cast<const uint4*>(
                hlo_in + (size_t)b * DH_) + o);
            *reinterpret_cast<uint4*>(h_hi_s + b * ROWB + o * 16) = vh;
            *reinterpret_cast<uint4*>(h_lo_s + b * ROWB + o * 16) = vl;
        }
        __syncthreads();

        // ---- mma mainloop ----
        float acc[2][4];
#pragma unroll
        for (int mt = 0; mt < 2; mt++)
#pragma unroll
            for (int r = 0; r < 4; r++) acc[mt][r] = 0.0f;

#pragma unroll
        for (int kt = 0; kt < 16; kt++) {
            const int kbase = kh * 256 + kt * 16;
            unsigned ah[2][4], al[2][4];
#pragma unroll
            for (int mt = 0; mt < 2; mt++) {
                const unsigned byte = (unsigned)((mt * 16 + rowoff) * ROWB
                                     + (kbase + koff) * 2);
                ldsm4(ah[mt][0], ah[mt][1], ah[mt][2], ah[mt][3], hs_hi_u + byte);
                ldsm4(al[mt][0], al[mt][1], al[mt][2], al[mt][3], hs_lo_u + byte);
            }
#pragma unroll
            for (int mt = 0; mt < 2; mt++) {
                mma_bf16(acc[mt][0], acc[mt][1], acc[mt][2], acc[mt][3],
                         ah[mt][0], ah[mt][1], ah[mt][2], ah[mt][3],
                         wh[kt][0], wh[kt][1]);
                mma_bf16(acc[mt][0], acc[mt][1], acc[mt][2], acc[mt][3],
                         ah[mt][0], ah[mt][1], ah[mt][2], ah[mt][3],
                         wl[kt][0], wl[kt][1]);
                mma_bf16(acc[mt][0], acc[mt][1], acc[mt][2], acc[mt][3],
                         al[mt][0], al[mt][1], al[mt][2], al[mt][3],
                         wh[kt][0], wh[kt][1]);
            }
        }

        // ---- write partials: zp[kh][b][c], c = gate*8 + colpair ----
        {
            const int g  = lane >> 2;
            const int cp = (lane & 3) * 2;
#pragma unroll
            for (int mt = 0; mt < 2; mt++) {
                const int b0 = mt * 16 + g;
                float2 v01 = make_float2(acc[mt][0], acc[mt][1]);
                float2 v23 = make_float2(acc[mt][2], acc[mt][3]);
                *reinterpret_cast<float2*>(
                    &zp[(kh * 32 + b0) * ZP_STRIDE + gate * 8 + cp]) = v01;
                *reinterpret_cast<float2*>(
                    &zp[(kh * 32 + b0 + 8) * ZP_STRIDE + gate * 8 + cp]) = v23;
            }
        }
        __syncthreads();

        // ---- elementwise LSTM (threads < 256; thread owns (b_e, jj_e)) ----
        if (tid < 256) {
            float z[4];
#pragma unroll
            for (int g = 0; g < 4; g++) {
                float s = gxv[g];
#pragma unroll
                for (int q = 0; q < 4; q++)
                    s += zp[(q * 32 + b_e) * ZP_STRIDE + g * 8 + jj_e];
                z[g] = s;
            }
            const float fg = sigf(z[0]);
            const float ig = sigf(z[1]);
            const float gg = tanhfast(z[2]);
            const float og = sigf(z[3]);

            const float cn = fg * c_s[tid] + ig * gg;
            c_s[tid] = cn;
            const float hn = og * tanhfast(cn);

            const int gj = j0 + jj_e;
            const size_t hidx = (size_t)b_e * DH_ + gj;
            const __nv_bfloat16 hh = __float2bfloat16(hn);
            hhi_out[hidx] = hh;
            hlo_out[hidx] = __float2bfloat16(hn - __bfloat162float(hh));
            g_hs[(size_t)t * B_ * DH_ + hidx] = hn;
        }

        // ---- grid barrier ----
        __syncthreads();
        if (t < S_ - 1) {
            if (tid == 0) {
                __threadfence();
                atomicAdd((unsigned*)&g_bar, 1u);
                const unsigned target = (unsigned)(NCTA_ * (t + 1));
                while (*barp < target) { }
                __threadfence();
            }
            __syncthreads();
        }
    }
}

// ----------------------------------------------------------------
// Phase 3: out = hs @ W_fc + b_fc  (FFMA2 version — measured best)
// ----------------------------------------------------------------
__global__ __launch_bounds__(256)
void gemm_fc_kernel(const float* __restrict__ Wfc, const float* __restrict__ bfc,
                    float* __restrict__ out)
{
    const int n0 = blockIdx.x * 128;
    const int m0 = blockIdx.y * 64;

    __shared__ float As[16 * 130];
    __shared__ float Bs[16 * 132];

    const int tid = threadIdx.x;
    const int tx  = tid & 15;
    const int ty  = tid >> 4;

    const int lm  = tid >> 2;
    const int lk4 = (tid & 3) * 4;
    const float* arow = g_hs + (size_t)(m0 + lm) * DH_;

    unsigned long long acc2[4][4];
#pragma unroll
    for (int i = 0; i < 4; i++)
#pragma unroll
        for (int j = 0; j < 4; j++) acc2[i][j] = 0ull;

    for (int k0 = 0; k0 < DH_; k0 += 16) {
        __syncthreads();
        float4 av = *reinterpret_cast<const float4*>(arow + k0 + lk4);
        *reinterpret_cast<unsigned long long*>(&As[(lk4 + 0) * 130 + 2 * lm]) = pack2(av.x, av.x);
        *reinterpret_cast<unsigned long long*>(&As[(lk4 + 1) * 130 + 2 * lm]) = pack2(av.y, av.y);
        *reinterpret_cast<unsigned long long*>(&As[(lk4 + 2) * 130 + 2 * lm]) = pack2(av.z, av.z);
        *reinterpret_cast<unsigned long long*>(&As[(lk4 + 3) * 130 + 2 * lm]) = pack2(av.w, av.w);
#pragma unroll
        for (int p = 0; p < 2; p++) {
            const int f  = tid + p * 256;
            const int r  = f >> 5;
            const int c4 = (f & 31) * 4;
            *reinterpret_cast<float4*>(&Bs[r * 132 + c4]) =
                *reinterpret_cast<const float4*>(Wfc + (size_t)(k0 + r) * DOUT_ + n0 + c4);
        }
        __syncthreads();

#pragma unroll
        for (int kk = 0; kk < 16; kk++) {
            unsigned long long a2[4], b2[4];
#pragma unroll
            for (int i = 0; i < 4; i++)
                a2[i] = *reinterpret_cast<const unsigned long long*>(
                    &As[kk * 130 + 2 * (ty * 4 + i)]);
#pragma unroll
            for (int jp = 0; jp < 4; jp++)
                b2[jp] = *reinterpret_cast<const unsigned long long*>(
                    &Bs[kk * 132 + 2 * tx + 32 * jp]);
#pragma unroll
            for (int i = 0; i < 4; i++)
#pragma unroll
                for (int jp = 0; jp < 4; jp++)
                    ffma2(acc2[i][jp], a2[i], b2[jp]);
        }
    }

#pragma unroll
    for (int i = 0; i < 4; i++) {
        const int m  = m0 + ty * 4 + i;
        const int bb = m & 31;
        const int tt = m >> 5;
        float* orow = out + ((size_t)bb * S_ + tt) * DOUT_;
#pragma unroll
        for (int jp = 0; jp < 4; jp++) {
            const int c0 = 2 * tx + 32 * jp;
            float2 v = unpack2(acc2[i][jp]);
            const float2 bv = *reinterpret_cast<const float2*>(&bfc[n0 + c0]);
            float2 o;
            o.x = v.x + bv.x;
            o.y = v.y + bv.y;
            *reinterpret_cast<float2*>(&orow[n0 + c0]) = o;
        }
    }
}

// ----------------------------------------------------------------
extern "C" void kernel_launch(void* const* d_in, const int* in_sizes, int n_in,
                              void* d_out, int out_size)
{
    const float* x   = (const float*)d_in[0];
    const float* Wf  = (const float*)d_in[1];
    const float* bf  = (const float*)d_in[2];
    const float* Wi  = (const float*)d_in[3];
    const float* bi  = (const float*)d_in[4];
    const float* Wg  = (const float*)d_in[5];
    const float* bg  = (const float*)d_in[6];
    const float* Wo  = (const float*)d_in[7];
    const float* bo  = (const float*)d_in[8];
    const float* Wfc = (const float*)d_in[9];
    const float* bfc = (const float*)d_in[10];
    float* out = (float*)d_out;

    static bool configured = false;
    if (!configured) {
        cudaFuncSetAttribute(lstm_persist_kernel,
                             cudaFuncAttributeMaxDynamicSharedMemorySize, SMEM_P_BYTES);
        configured = true;
    }

    init_state_kernel<<<(B_ * DH_ + 255) / 256, 256>>>();

    {
        dim3 grid(NG_ / 64, (B_ * S_) / 64);
        dim3 block(16, 16);
        gemm_gatesx_kernel<<<grid, block>>>(x, Wf, bf, Wi, bi, Wg, bg, Wo, bo);
    }

    lstm_persist_kernel<<<NCTA_, 512, SMEM_P_BYTES>>>(Wf, Wi, Wg, Wo);

    {
        dim3 grid(DOUT_ / 128, (B_ * S_) / 64);
        gemm_fc_kernel<<<grid, 256>>>(Wfc, bfc, out);
    }
}

// round 7
// speedup vs baseline: 2.9038x; 1.4035x over previous
#include <cuda_runtime.h>
#include <cuda_bf16.h>
#include <math.h>

// Problem constants
#define B_    32
#define S_    512
#define DIN_  512
#define DH_   1024
#define DOUT_ 512
#define NG_   4096   // 4 * DH_
#define M_    (B_ * S_)   // 16384

#define NCTA_  128

// ---- persistent mma kernel smem layout (bytes) ----
#define ROWB      2064                  // h plane row stride: 1024*2 + 16 pad
#define HPLANE_B  (32 * ROWB)           // 66048
#define ZP_OFF    (2 * HPLANE_B)        // 132096
#define ZP_STRIDE 34                    // floats per zp row
#define ZP_B      (4 * 32 * ZP_STRIDE * 4)   // 17408
#define CS_OFF    (ZP_OFF + ZP_B)       // 149504
#define SMEM_P_BYTES (CS_OFF + 256 * 4) // 150528

// -------- scratch (device globals; no allocation allowed) --------
__device__ float g_gatesx[S_ * B_ * NG_];        // [m=t*32+b][4096], n = gate*1024+j
__device__ __nv_bfloat16 g_xhi[M_ * DIN_];       // A planes for gatesx: [m][512]
__device__ __nv_bfloat16 g_xlo[M_ * DIN_];
__device__ __nv_bfloat16 g_whx[DIN_ * NG_];      // B planes: [k][4096]
__device__ __nv_bfloat16 g_wlx[DIN_ * NG_];
__device__ float g_ball[NG_];                    // combined bias
__device__ __nv_bfloat16 g_fchi[DH_ * DOUT_];    // [k][512]
__device__ __nv_bfloat16 g_fclo[DH_ * DOUT_];
__device__ __nv_bfloat16 g_hshi[S_ * B_ * DH_];  // hs planes: [m=t*32+b][1024]
__device__ __nv_bfloat16 g_hslo[S_ * B_ * DH_];
__device__ __nv_bfloat16 g_hhi[2][B_ * DH_];
__device__ __nv_bfloat16 g_hlo[2][B_ * DH_];
__device__ unsigned g_bar;

// ---------------- helpers ----------------
__device__ __forceinline__ float sigf(float x) {
    return __fdividef(1.0f, 1.0f + __expf(-x));
}
__device__ __forceinline__ float tanhfast(float x) {
    return __fdividef(2.0f, 1.0f + __expf(-2.0f * x)) - 1.0f;
}
__device__ __forceinline__ unsigned s2u(const void* p) {
    return (unsigned)__cvta_generic_to_shared(p);
}
__device__ __forceinline__ void split2(float a, float b, unsigned& hi, unsigned& lo) {
    __nv_bfloat16 ah = __float2bfloat16(a);
    __nv_bfloat16 bh = __float2bfloat16(b);
    float ar = a - __bfloat162float(ah);
    float br = b - __bfloat162float(bh);
    __nv_bfloat162 hv; hv.x = ah; hv.y = bh;
    __nv_bfloat162 lv; lv.x = __float2bfloat16(ar); lv.y = __float2bfloat16(br);
    hi = *reinterpret_cast<unsigned*>(&hv);
    lo = *reinterpret_cast<unsigned*>(&lv);
}
__device__ __forceinline__ void ldsm4(unsigned& r0, unsigned& r1, unsigned& r2,
                                      unsigned& r3, unsigned addr) {
    asm volatile("ldmatrix.sync.aligned.m8n8.x4.shared.b16 {%0,%1,%2,%3}, [%4];"
                 : "=r"(r0), "=r"(r1), "=r"(r2), "=r"(r3) : "r"(addr));
}
__device__ __forceinline__ void ldsm4t(unsigned& r0, unsigned& r1, unsigned& r2,
                                       unsigned& r3, unsigned addr) {
    asm volatile("ldmatrix.sync.aligned.m8n8.x4.trans.shared.b16 {%0,%1,%2,%3}, [%4];"
                 : "=r"(r0), "=r"(r1), "=r"(r2), "=r"(r3) : "r"(addr));
}
__device__ __forceinline__ void mma_bf16(float& c0, float& c1, float& c2, float& c3,
                                         unsigned a0, unsigned a1, unsigned a2, unsigned a3,
                                         unsigned b0, unsigned b1) {
    asm volatile("mma.sync.aligned.m16n8k16.row.col.f32.bf16.bf16.f32 "
                 "{%0,%1,%2,%3},{%4,%5,%6,%7},{%8,%9},{%0,%1,%2,%3};"
                 : "+f"(c0), "+f"(c1), "+f"(c2), "+f"(c3)
                 : "r"(a0), "r"(a1), "r"(a2), "r"(a3), "r"(b0), "r"(b1));
}

// ----------------------------------------------------------------
__global__ void init_state_kernel() {
    int i = blockIdx.x * blockDim.x + threadIdx.x;
    if (i < B_ * DH_) {
        g_hhi[0][i] = __float2bfloat16(0.0f);
        g_hlo[0][i] = __float2bfloat16(0.0f);
    }
    if (i == 0) g_bar = 0u;
}

// ----------------------------------------------------------------
// Convert kernels: fp32 -> bf16 hi/lo planes
// ----------------------------------------------------------------
__global__ void conv_w_kernel(const float* __restrict__ Wf, const float* __restrict__ Wi,
                              const float* __restrict__ Wg, const float* __restrict__ Wo,
                              const float* __restrict__ bf, const float* __restrict__ bi,
                              const float* __restrict__ bg, const float* __restrict__ bo)
{
    const int i = blockIdx.x * 256 + threadIdx.x;   // over 512*4096
    if (i < DIN_ * NG_) {
        const int k = i >> 12, n = i & 4095, gate = n >> 10, j = n & 1023;
        const float* W = (gate == 0) ? Wf : (gate == 1) ? Wi : (gate == 2) ? Wg : Wo;
        const float v = W[(size_t)k * DH_ + j];
        const __nv_bfloat16 h = __float2bfloat16(v);
        g_whx[i] = h;
        g_wlx[i] = __float2bfloat16(v - __bfloat162float(h));
    }
    if (i < NG_) {
        const int gate = i >> 10, j = i & 1023;
        const float* bb = (gate == 0) ? bf : (gate == 1) ? bi : (gate == 2) ? bg : bo;
        g_ball[i] = bb[j];
    }
}

__global__ void conv_x_kernel(const float* __restrict__ x)
{
    const int i = blockIdx.x * 256 + threadIdx.x;   // over M_*DIN_
    const int m = i >> 9, k = i & 511;
    const int b = m & 31, t = m >> 5;
    const float v = x[((size_t)b * S_ + t) * DIN_ + k];
    const __nv_bfloat16 h = __float2bfloat16(v);
    g_xhi[i] = h;
    g_xlo[i] = __float2bfloat16(v - __bfloat162float(h));
}

__global__ void conv_fc_kernel(const float* __restrict__ Wfc)
{
    const int i = blockIdx.x * 256 + threadIdx.x;   // over DH_*DOUT_
    const float v = Wfc[i];
    const __nv_bfloat16 h = __float2bfloat16(v);
    g_fchi[i] = h;
    g_fclo[i] = __float2bfloat16(v - __bfloat162float(h));
}

// ----------------------------------------------------------------
// Phase 1: gates_x = x @ Wx + bias via bf16-split mma.
// CTA 128m x 128n, 256 thr (8 warps, 2m x 4n layout, warp tile 64x32).
// k-chunk 32. A smem stride 40 halves (80B), B stride 136 halves (272B):
// both conflict-free for ldmatrix.
// ----------------------------------------------------------------
__global__ __launch_bounds__(256)
void gemm_gatesx_mma()
{
    const int n0 = blockIdx.x * 128;
    const int m0 = blockIdx.y * 128;

    __shared__ __align__(16) __nv_bfloat16 Ahi_s[128 * 40];
    __shared__ __align__(16) __nv_bfloat16 Alo_s[128 * 40];
    __shared__ __align__(16) __nv_bfloat16 Bhi_s[32 * 136];
    __shared__ __align__(16) __nv_bfloat16 Blo_s[32 * 136];

    const int tid = threadIdx.x, lane = tid & 31, warp = tid >> 5;
    const int wm = (warp >> 2) * 64, wn = (warp & 3) * 32;

    const int selA = lane >> 3;
    const int rowA = (selA & 1) * 8 + (lane & 7);
    const int kA   = (selA >> 1) * 8;
    const int qb   = lane >> 3;
    const int rowB = (qb & 1) * 8 + (lane & 7);
    const int nB   = (qb >> 1) * 8;

    const unsigned ahi_u = s2u(Ahi_s), alo_u = s2u(Alo_s);
    const unsigned bhi_u = s2u(Bhi_s), blo_u = s2u(Blo_s);

    float acc[4][4][4];
#pragma unroll
    for (int mf = 0; mf < 4; mf++)
#pragma unroll
        for (int nf = 0; nf < 4; nf++)
#pragma unroll
            for (int r = 0; r < 4; r++) acc[mf][nf][r] = 0.0f;

    for (int k0 = 0; k0 < DIN_; k0 += 32) {
        __syncthreads();
#pragma unroll
        for (int p = 0; p < 2; p++) {
            const int c  = tid + p * 256;
            const int m  = c >> 2, k8 = (c & 3) * 8;
            *reinterpret_cast<uint4*>(&Ahi_s[m * 40 + k8]) =
                *reinterpret_cast<const uint4*>(&g_xhi[(size_t)(m0 + m) * DIN_ + k0 + k8]);
            *reinterpret_cast<uint4*>(&Alo_s[m * 40 + k8]) =
                *reinterpret_cast<const uint4*>(&g_xlo[(size_t)(m0 + m) * DIN_ + k0 + k8]);
            const int kr = c >> 4, n8 = (c & 15) * 8;
            *reinterpret_cast<uint4*>(&Bhi_s[kr * 136 + n8]) =
                *reinterpret_cast<const uint4*>(&g_whx[(size_t)(k0 + kr) * NG_ + n0 + n8]);
            *reinterpret_cast<uint4*>(&Blo_s[kr * 136 + n8]) =
                *reinterpret_cast<const uint4*>(&g_wlx[(size_t)(k0 + kr) * NG_ + n0 + n8]);
        }
        __syncthreads();

#pragma unroll
        for (int ks = 0; ks < 2; ks++) {
            const int kb = ks * 16;
            unsigned ah[4][4], al[4][4];
#pragma unroll
            for (int mf = 0; mf < 4; mf++) {
                const unsigned off = (unsigned)((wm + mf * 16 + rowA) * 80 + (kb + kA) * 2);
                ldsm4(ah[mf][0], ah[mf][1], ah[mf][2], ah[mf][3], ahi_u + off);
                ldsm4(al[mf][0], al[mf][1], al[mf][2], al[mf][3], alo_u + off);
            }
            unsigned bh[4][2], bl[4][2];
#pragma unroll
            for (int np = 0; np < 2; np++) {
                const unsigned off = (unsigned)((kb + rowB) * 272 + (wn + np * 16 + nB) * 2);
                unsigned r0, r1, r2, r3;
                ldsm4t(r0, r1, r2, r3, bhi_u + off);
                bh[np * 2][0] = r0; bh[np * 2][1] = r1;
                bh[np * 2 + 1][0] = r2; bh[np * 2 + 1][1] = r3;
                ldsm4t(r0, r1, r2, r3, blo_u + off);
                bl[np * 2][0] = r0; bl[np * 2][1] = r1;
                bl[np * 2 + 1][0] = r2; bl[np * 2 + 1][1] = r3;
            }
#pragma unroll
            for (int mf = 0; mf < 4; mf++)
#pragma unroll
                for (int nf = 0; nf < 4; nf++) {
                    mma_bf16(acc[mf][nf][0], acc[mf][nf][1], acc[mf][nf][2], acc[mf][nf][3],
                             ah[mf][0], ah[mf][1], ah[mf][2], ah[mf][3],
                             bh[nf][0], bh[nf][1]);
                    mma_bf16(acc[mf][nf][0], acc[mf][nf][1], acc[mf][nf][2], acc[mf][nf][3],
                             ah[mf][0], ah[mf][1], ah[mf][2], ah[mf][3],
                             bl[nf][0], bl[nf][1]);
                    mma_bf16(acc[mf][nf][0], acc[mf][nf][1], acc[mf][nf][2], acc[mf][nf][3],
                             al[mf][0], al[mf][1], al[mf][2], al[mf][3],
                             bh[nf][0], bh[nf][1]);
                }
        }
    }

    // epilogue: add bias, store fp32
#pragma unroll
    for (int mf = 0; mf < 4; mf++) {
        const int r = m0 + wm + mf * 16 + (lane >> 2);
#pragma unroll
        for (int nf = 0; nf < 4; nf++) {
            const int c = n0 + wn + nf * 8 + (lane & 3) * 2;
            const float2 bv = *reinterpret_cast<const float2*>(&g_ball[c]);
            float2 v0, v1;
            v0.x = acc[mf][nf][0] + bv.x; v0.y = acc[mf][nf][1] + bv.y;
            v1.x = acc[mf][nf][2] + bv.x; v1.y = acc[mf][nf][3] + bv.y;
            *reinterpret_cast<float2*>(&g_gatesx[(size_t)r * NG_ + c]) = v0;
            *reinterpret_cast<float2*>(&g_gatesx[(size_t)(r + 8) * NG_ + c]) = v1;
        }
    }
}

// ----------------------------------------------------------------
// Phase 3: out = hs @ W_fc + b_fc via bf16-split mma. K=1024, N=512.
// ----------------------------------------------------------------
__global__ __launch_bounds__(256)
void gemm_fc_mma(const float* __restrict__ bfc, float* __restrict__ out)
{
    const int n0 = blockIdx.x * 128;
    const int m0 = blockIdx.y * 128;

    __shared__ __align__(16) __nv_bfloat16 Ahi_s[128 * 40];
    __shared__ __align__(16) __nv_bfloat16 Alo_s[128 * 40];
    __shared__ __align__(16) __nv_bfloat16 Bhi_s[32 * 136];
    __shared__ __align__(16) __nv_bfloat16 Blo_s[32 * 136];

    const int tid = threadIdx.x, lane = tid & 31, warp = tid >> 5;
    const int wm = (warp >> 2) * 64, wn = (warp & 3) * 32;

    const int selA = lane >> 3;
    const int rowA = (selA & 1) * 8 + (lane & 7);
    const int kA   = (selA >> 1) * 8;
    const int qb   = lane >> 3;
    const int rowB = (qb & 1) * 8 + (lane & 7);
    const int nB   = (qb >> 1) * 8;

    const unsigned ahi_u = s2u(Ahi_s), alo_u = s2u(Alo_s);
    const unsigned bhi_u = s2u(Bhi_s), blo_u = s2u(Blo_s);

    float acc[4][4][4];
#pragma unroll
    for (int mf = 0; mf < 4; mf++)
#pragma unroll
        for (int nf = 0; nf < 4; nf++)
#pragma unroll
            for (int r = 0; r < 4; r++) acc[mf][nf][r] = 0.0f;

    for (int k0 = 0; k0 < DH_; k0 += 32) {
        __syncthreads();
#pragma unroll
        for (int p = 0; p < 2; p++) {
            const int c  = tid + p * 256;
            const int m  = c >> 2, k8 = (c & 3) * 8;
            *reinterpret_cast<uint4*>(&Ahi_s[m * 40 + k8]) =
                *reinterpret_cast<const uint4*>(&g_hshi[(size_t)(m0 + m) * DH_ + k0 + k8]);
            *reinterpret_cast<uint4*>(&Alo_s[m * 40 + k8]) =
                *reinterpret_cast<const uint4*>(&g_hslo[(size_t)(m0 + m) * DH_ + k0 + k8]);
            const int kr = c >> 4, n8 = (c & 15) * 8;
            *reinterpret_cast<uint4*>(&Bhi_s[kr * 136 + n8]) =
                *reinterpret_cast<const uint4*>(&g_fchi[(size_t)(k0 + kr) * DOUT_ + n0 + n8]);
            *reinterpret_cast<uint4*>(&Blo_s[kr * 136 + n8]) =
                *reinterpret_cast<const uint4*>(&g_fclo[(size_t)(k0 + kr) * DOUT_ + n0 + n8]);
        }
        __syncthreads();

#pragma unroll
        for (int ks = 0; ks < 2; ks++) {
            const int kb = ks * 16;
            unsigned ah[4][4], al[4][4];
#pragma unroll
            for (int mf = 0; mf < 4; mf++) {
                const unsigned off = (unsigned)((wm + mf * 16 + rowA) * 80 + (kb + kA) * 2);
                ldsm4(ah[mf][0], ah[mf][1], ah[mf][2], ah[mf][3], ahi_u + off);
                ldsm4(al[mf][0], al[mf][1], al[mf][2], al[mf][3], alo_u + off);
            }
            unsigned bh[4][2], bl[4][2];
#pragma unroll
            for (int np = 0; np < 2; np++) {
                const unsigned off = (unsigned)((kb + rowB) * 272 + (wn + np * 16 + nB) * 2);
                unsigned r0, r1, r2, r3;
                ldsm4t(r0, r1, r2, r3, bhi_u + off);
                bh[np * 2][0] = r0; bh[np * 2][1] = r1;
                bh[np * 2 + 1][0] = r2; bh[np * 2 + 1][1] = r3;
                ldsm4t(r0, r1, r2, r3, blo_u + off);
                bl[np * 2][0] = r0; bl[np * 2][1] = r1;
                bl[np * 2 + 1][0] = r2; bl[np * 2 + 1][1] = r3;
            }
#pragma unroll
            for (int mf = 0; mf < 4; mf++)
#pragma unroll
                for (int nf = 0; nf < 4; nf++) {
                    mma_bf16(acc[mf][nf][0], acc[mf][nf][1], acc[mf][nf][2], acc[mf][nf][3],
                             ah[mf][0], ah[mf][1], ah[mf][2], ah[mf][3],
                             bh[nf][0], bh[nf][1]);
                    mma_bf16(acc[mf][nf][0], acc[mf][nf][1], acc[mf][nf][2], acc[mf][nf][3],
                             ah[mf][0], ah[mf][1], ah[mf][2], ah[mf][3],
                             bl[nf][0], bl[nf][1]);
                    mma_bf16(acc[mf][nf][0], acc[mf][nf][1], acc[mf][nf][2], acc[mf][nf][3],
                             al[mf][0], al[mf][1], al[mf][2], al[mf][3],
                             bh[nf][0], bh[nf][1]);
                }
        }
    }

#pragma unroll
    for (int mf = 0; mf < 4; mf++) {
        const int r = m0 + wm + mf * 16 + (lane >> 2);
#pragma unroll
        for (int nf = 0; nf < 4; nf++) {
            const int c = n0 + wn + nf * 8 + (lane & 3) * 2;
            const float2 bv = *reinterpret_cast<const float2*>(&bfc[c]);
            float2 v0, v1;
            v0.x = acc[mf][nf][0] + bv.x; v0.y = acc[mf][nf][1] + bv.y;
            v1.x = acc[mf][nf][2] + bv.x; v1.y = acc[mf][nf][3] + bv.y;
            {
                const int bb = r & 31, tt = r >> 5;
                *reinterpret_cast<float2*>(&out[((size_t)bb * S_ + tt) * DOUT_ + c]) = v0;
            }
            {
                const int r1i = r + 8;
                const int bb = r1i & 31, tt = r1i >> 5;
                *reinterpret_cast<float2*>(&out[((size_t)bb * S_ + tt) * DOUT_ + c]) = v1;
            }
        }
    }
}

// ----------------------------------------------------------------
// Phase 2: PERSISTENT recurrence (unchanged from R5 except hs bf16 planes).
// ----------------------------------------------------------------
__global__ __launch_bounds__(512, 1)
void lstm_persist_kernel(const float* __restrict__ Wf, const float* __restrict__ Wi,
                         const float* __restrict__ Wg, const float* __restrict__ Wo)
{
    extern __shared__ char smem[];
    char*  h_hi_s = smem;
    char*  h_lo_s = smem + HPLANE_B;
    float* zp     = reinterpret_cast<float*>(smem + ZP_OFF);
    float* c_s    = reinterpret_cast<float*>(smem + CS_OFF);

    const int tid  = threadIdx.x;
    const int lane = tid & 31;
    const int warp = tid >> 5;
    const int j0   = blockIdx.x * 8;

    const int kh   = warp >> 2;
    const int gate = warp & 3;
    const float* Wsel = (gate == 0) ? Wf : (gate == 1) ? Wi : (gate == 2) ? Wg : Wo;

    const int jj = lane >> 2;
    const int kr = (lane & 3) * 2;
    unsigned wh[16][2], wl[16][2];
#pragma unroll
    for (int kt = 0; kt < 16; kt++) {
        const int kb = kh * 256 + kt * 16 + kr;
        const float w0a = Wsel[(size_t)(512 + kb + 0) * DH_ + j0 + jj];
        const float w0b = Wsel[(size_t)(512 + kb + 1) * DH_ + j0 + jj];
        const float w1a = Wsel[(size_t)(512 + kb + 8) * DH_ + j0 + jj];
        const float w1b = Wsel[(size_t)(512 + kb + 9) * DH_ + j0 + jj];
        split2(w0a, w0b, wh[kt][0], wl[kt][0]);
        split2(w1a, w1b, wh[kt][1], wl[kt][1]);
    }

    if (tid < 256) c_s[tid] = 0.0f;
    __syncthreads();

    const int sel    = lane >> 3;
    const int rowoff = ((sel & 1) * 8) + (lane & 7);
    const int koff   = (sel >> 1) * 8;

    const unsigned hs_hi_u = s2u(h_hi_s);
    const unsigned hs_lo_u = s2u(h_lo_s);

    const int b_e  = tid >> 3;
    const int jj_e = tid & 7;

    volatile unsigned* barp = &g_bar;

    for (int t = 0; t < S_; ++t) {
        const __nv_bfloat16* __restrict__ hhi_in = g_hhi[t & 1];
        const __nv_bfloat16* __restrict__ hlo_in = g_hlo[t & 1];
        __nv_bfloat16* __restrict__ hhi_out = g_hhi[(t + 1) & 1];
        __nv_bfloat16* __restrict__ hlo_out = g_hlo[(t + 1) & 1];
        const float* __restrict__ gx_t = g_gatesx + (size_t)t * B_ * NG_;

        float gxv[4];
        if (tid < 256) {
#pragma unroll
            for (int g = 0; g < 4; g++)
                gxv[g] = __ldg(&gx_t[(size_t)b_e * NG_ + g * DH_ + j0 + jj_e]);
        }

#pragma unroll
        for (int q = 0; q < 8; q++) {
            const int chunk = tid + q * 512;
            const int b = chunk >> 7;
            const int o = chunk & 127;
            const uint4 vh = __ldcg(reinterpret_cast<const uint4*>(
                hhi_in + (size_t)b * DH_) + o);
            const uint4 vl = __ldcg(reinterpret_cast<const uint4*>(
                hlo_in + (size_t)b * DH_) + o);
            *reinterpret_cast<uint4*>(h_hi_s + b * ROWB + o * 16) = vh;
            *reinterpret_cast<uint4*>(h_lo_s + b * ROWB + o * 16) = vl;
        }
        __syncthreads();

        float acc[2][4];
#pragma unroll
        for (int mt = 0; mt < 2; mt++)
#pragma unroll
            for (int r = 0; r < 4; r++) acc[mt][r] = 0.0f;

#pragma unroll
        for (int kt = 0; kt < 16; kt++) {
            const int kbase = kh * 256 + kt * 16;
            unsigned ah[2][4], al[2][4];
#pragma unroll
            for (int mt = 0; mt < 2; mt++) {
                const unsigned byte = (unsigned)((mt * 16 + rowoff) * ROWB
                                     + (kbase + koff) * 2);
                ldsm4(ah[mt][0], ah[mt][1], ah[mt][2], ah[mt][3], hs_hi_u + byte);
                ldsm4(al[mt][0], al[mt][1], al[mt][2], al[mt][3], hs_lo_u + byte);
            }
#pragma unroll
            for (int mt = 0; mt < 2; mt++) {
                mma_bf16(acc[mt][0], acc[mt][1], acc[mt][2], acc[mt][3],
                         ah[mt][0], ah[mt][1], ah[mt][2], ah[mt][3],
                         wh[kt][0], wh[kt][1]);
                mma_bf16(acc[mt][0], acc[mt][1], acc[mt][2], acc[mt][3],
                         ah[mt][0], ah[mt][1], ah[mt][2], ah[mt][3],
                         wl[kt][0], wl[kt][1]);
                mma_bf16(acc[mt][0], acc[mt][1], acc[mt][2], acc[mt][3],
                         al[mt][0], al[mt][1], al[mt][2], al[mt][3],
                         wh[kt][0], wh[kt][1]);
            }
        }

        {
            const int g  = lane >> 2;
            const int cp = (lane & 3) * 2;
#pragma unroll
            for (int mt = 0; mt < 2; mt++) {
                const int b0 = mt * 16 + g;
                float2 v01 = make_float2(acc[mt][0], acc[mt][1]);
                float2 v23 = make_float2(acc[mt][2], acc[mt][3]);
                *reinterpret_cast<float2*>(
                    &zp[(kh * 32 + b0) * ZP_STRIDE + gate * 8 + cp]) = v01;
                *reinterpret_cast<float2*>(
                    &zp[(kh * 32 + b0 + 8) * ZP_STRIDE + gate * 8 + cp]) = v23;
            }
        }
        __syncthreads();

        if (tid < 256) {
            float z[4];
#pragma unroll
            for (int g = 0; g < 4; g++) {
                float s = gxv[g];
#pragma unroll
                for (int q = 0; q < 4; q++)
                    s += zp[(q * 32 + b_e) * ZP_STRIDE + g * 8 + jj_e];
                z[g] = s;
            }
            const float fg = sigf(z[0]);
            const float ig = sigf(z[1]);
            const float gg = tanhfast(z[2]);
            const float og = sigf(z[3]);

            const float cn = fg * c_s[tid] + ig * gg;
            c_s[tid] = cn;
            const float hn = og * tanhfast(cn);

            const int gj = j0 + jj_e;
            const size_t hidx = (size_t)b_e * DH_ + gj;
            const __nv_bfloat16 hh = __float2bfloat16(hn);
            const __nv_bfloat16 hl = __float2bfloat16(hn - __bfloat162float(hh));
            hhi_out[hidx] = hh;
            hlo_out[hidx] = hl;
            g_hshi[(size_t)t * B_ * DH_ + hidx] = hh;
            g_hslo[(size_t)t * B_ * DH_ + hidx] = hl;
        }

        __syncthreads();
        if (t < S_ - 1) {
            if (tid == 0) {
                __threadfence();
                atomicAdd((unsigned*)&g_bar, 1u);
                const unsigned target = (unsigned)(NCTA_ * (t + 1));
                while (*barp < target) { }
                __threadfence();
            }
            __syncthreads();
        }
    }
}

// ----------------------------------------------------------------
extern "C" void kernel_launch(void* const* d_in, const int* in_sizes, int n_in,
                              void* d_out, int out_size)
{
    const float* x   = (const float*)d_in[0];
    const float* Wf  = (const float*)d_in[1];
    const float* bf  = (const float*)d_in[2];
    const float* Wi  = (const float*)d_in[3];
    const float* bi  = (const float*)d_in[4];
    const float* Wg  = (const float*)d_in[5];
    const float* bg  = (const float*)d_in[6];
    const float* Wo  = (const float*)d_in[7];
    const float* bo  = (const float*)d_in[8];
    const float* Wfc = (const float*)d_in[9];
    const float* bfc = (const float*)d_in[10];
    float* out = (float*)d_out;

    static bool configured = false;
    if (!configured) {
        cudaFuncSetAttribute(lstm_persist_kernel,
                             cudaFuncAttributeMaxDynamicSharedMemorySize, SMEM_P_BYTES);
        configured = true;
    }

    init_state_kernel<<<(B_ * DH_ + 255) / 256, 256>>>();

    // converts
    conv_w_kernel<<<(DIN_ * NG_ + 255) / 256, 256>>>(Wf, Wi, Wg, Wo, bf, bi, bg, bo);
    conv_x_kernel<<<(M_ * DIN_ + 255) / 256, 256>>>(x);
    conv_fc_kernel<<<(DH_ * DOUT_ + 255) / 256, 256>>>(Wfc);

    // Phase 1
    {
        dim3 grid(NG_ / 128, M_ / 128);
        gemm_gatesx_mma<<<grid, 256>>>();
    }

    // Phase 2
    lstm_persist_kernel<<<NCTA_, 512, SMEM_P_BYTES>>>(Wf, Wi, Wg, Wo);

    // Phase 3
    {
        dim3 grid(DOUT_ / 128, M_ / 128);
        gemm_fc_mma<<<grid, 256>>>(bfc, out);
    }
}